// round 16
// baseline (speedup 1.0000x reference)
#include <cuda_runtime.h>
#include <cuda_fp16.h>
#include <cstdint>

// Problem constants: B=8, S=2048, D=256
static constexpr int Bn = 8;
static constexpr int Sn = 2048;
static constexpr int Dn = 256;
static constexpr int MROWS = Bn * Sn;   // 16384

// ---------------- device scratch (no cudaMalloc allowed) ----------------
// Unified fp16 vector layout: tensors split into (128-row x 64-k) tiles of 16 KB.
// Vector (m,q,slotpos): slot = slotpos ^ ((q&1)<<2), k = (slot>>2)*16 + (slot&3)*2,
// r = 16m + q. Vector = {T[r][k],T[r][k+1], T[r+8][k],T[r+8][k+1],
//                        T[r][k+8],T[r][k+9], T[r+8][k+8],T[r+8][k+9]}.
__device__ __align__(16) __half g_headH[MROWS * Dn];
__device__ __align__(16) __half g_depH [MROWS * Dn];
__device__ __align__(16) __half g_Ph   [MROWS * Dn];
__device__ __align__(16) __half g_UTH  [Dn * Dn];
__device__ float g_hs[MROWS];
__device__ float g_ds[MROWS];

static constexpr int TILE_H = 8192;     // halves per (128x64) tile

__device__ __forceinline__ uint32_t pack2(float lo, float hi) {
    __half2 h = __floats2half2_rn(lo, hi);
    return *(uint32_t*)&h;
}

// ---------------- prep: head/dep register repack + dots | U->UTH ----------------
static constexpr int HD_BLOCKS = (2 * MROWS) / 32;   // 1024 (32 rows/block)
static constexpr int UT_BLOCKS = 16;

__global__ void __launch_bounds__(256) prep_all(const float* __restrict__ head,
                                                const float* __restrict__ dep,
                                                const float* __restrict__ W,
                                                const float* __restrict__ U) {
    int bid = blockIdx.x;
    int tid = threadIdx.x;

    if (bid < HD_BLOCKS) {
        int idx0 = bid * 32;
        bool isHead = idx0 < MROWS;
        const float* src = isHead ? head : dep;
        __half* dstH     = isHead ? g_headH : g_depH;
        float* dotDst    = isHead ? g_hs : g_ds;
        const float* wvp = isHead ? W : (W + Dn);
        int r0 = (isHead ? idx0 : idx0 - MROWS) + (tid >> 7) * 16;  // 16-row group
        int t = tid & 127;
        int q = t >> 4;                  // 0..7
        int kc = (t >> 2) & 3;           // 0..3
        int s = t & 3;                   // 0..3
        int row = r0 + q;
        int k0 = kc * 64 + s * 16;

        float av[16], bv[16], wv[16];
        {
            const float4* p0 = (const float4*)(src + (size_t)row * Dn + k0);
            const float4* p1 = (const float4*)(src + (size_t)(row + 8) * Dn + k0);
            const float4* pw = (const float4*)(wvp + k0);
            #pragma unroll
            for (int i = 0; i < 4; i++) {
                float4 x = p0[i];
                av[i*4+0]=x.x; av[i*4+1]=x.y; av[i*4+2]=x.z; av[i*4+3]=x.w;
                float4 y = p1[i];
                bv[i*4+0]=y.x; bv[i*4+1]=y.y; bv[i*4+2]=y.z; bv[i*4+3]=y.w;
                float4 z = pw[i];
                wv[i*4+0]=z.x; wv[i*4+1]=z.y; wv[i*4+2]=z.z; wv[i*4+3]=z.w;
            }
        }

        // partial dots over these 16 cols, reduce across the 16 threads sharing q
        float pd0 = 0.f, pd1 = 0.f;
        #pragma unroll
        for (int i = 0; i < 16; i++) { pd0 += av[i] * wv[i]; pd1 += bv[i] * wv[i]; }
        #pragma unroll
        for (int o = 8; o; o >>= 1) {
            pd0 += __shfl_down_sync(0xFFFFFFFFu, pd0, o, 16);
            pd1 += __shfl_down_sync(0xFFFFFFFFu, pd1, o, 16);
        }
        if ((t & 15) == 0) { dotDst[row] = pd0; dotDst[row + 8] = pd1; }

        // emit 4 vectors (kq = 0..3) straight from registers
        int rowtile = r0 >> 7;
        int m = (r0 & 127) >> 4;
        int xq = (q & 1) << 2;
        #pragma unroll
        for (int kq = 0; kq < 4; kq++) {
            int kl = kq * 2;             // col offset within the 16-col group
            uint4 o;
            o.x = pack2(av[kl],     av[kl + 1]);
            o.y = pack2(bv[kl],     bv[kl + 1]);
            o.z = pack2(av[kl + 8], av[kl + 9]);
            o.w = pack2(bv[kl + 8], bv[kl + 9]);
            int slotpos = (s * 4 + kq) ^ xq;
            size_t off = ((size_t)(rowtile * 4 + kc)) * TILE_H
                       + ((m * 8 + q) * 16 + slotpos) * 8;
            *(uint4*)(dstH + off) = o;
        }
        return;
    }

    // ---- UT: UTH[e-tile] from U via smem transpose (16 blocks) ----
    {
        __shared__ float s16[16][264];
        int tb = bid - HD_BLOCKS;
        int r0 = tb * 16;               // e base
        #pragma unroll
        for (int i = 0; i < 16; i++) {
            int d = i * 16 + (tid >> 4);
            int e = tid & 15;
            s16[e][d] = U[(size_t)d * Dn + r0 + e];
        }
        __syncthreads();
        int rowtile = r0 >> 7;
        int m = (r0 & 127) >> 4;
        #pragma unroll
        for (int it = 0; it < 2; it++) {
            int v = it * 256 + tid;     // 0..511
            int kc = v >> 7;
            int u = v & 127;
            int q = u >> 4;
            int slotpos = u & 15;
            int slot = slotpos ^ ((q & 1) << 2);
            int k = kc * 64 + (slot >> 2) * 16 + (slot & 3) * 2;
            uint4 o;
            o.x = pack2(s16[q][k],         s16[q][k + 1]);
            o.y = pack2(s16[q + 8][k],     s16[q + 8][k + 1]);
            o.z = pack2(s16[q][k + 8],     s16[q][k + 9]);
            o.w = pack2(s16[q + 8][k + 8], s16[q + 8][k + 9]);
            size_t off = ((size_t)(rowtile * 4 + kc)) * TILE_H
                       + ((m * 8 + q) * 16 + slotpos) * 8;
            *(uint4*)(g_UTH + off) = o;
        }
    }
}

// ---------------- fp16 MMA GEMM: CTA 128x128, 4 warps, warp tile 64x64, BK=64 ----------------
static constexpr int BM = 128, BN = 128, TH = 128;
static constexpr int STAGES = 3;
static constexpr uint32_t TILE_BYTES = 16384;                 // 128x64 fp16
static constexpr uint32_t STAGE_BYTES = 2 * TILE_BYTES;       // A + B
static constexpr uint32_t EXTRA_OFF = STAGES * STAGE_BYTES;   // 98304
static constexpr uint32_t SMEM_BYTES = EXTRA_OFF + 1024;

__device__ __forceinline__ uint32_t smem_u32(const void* p) {
    uint32_t a;
    asm("{ .reg .u64 t; cvta.to.shared.u64 t, %1; cvt.u32.u64 %0, t; }"
        : "=r"(a) : "l"(p));
    return a;
}
__device__ __forceinline__ void cpasync16(uint32_t dst, const void* src) {
    size_t g = __cvta_generic_to_global(src);
    asm volatile("cp.async.cg.shared.global [%0], [%1], 16;" :: "r"(dst), "l"(g));
}
__device__ __forceinline__ void mma_f16(float* c, const uint32_t* a, const uint32_t* b) {
    asm volatile(
        "mma.sync.aligned.m16n8k16.row.col.f32.f16.f16.f32 "
        "{%0,%1,%2,%3}, {%4,%5,%6,%7}, {%8,%9}, {%0,%1,%2,%3};"
        : "+f"(c[0]), "+f"(c[1]), "+f"(c[2]), "+f"(c[3])
        : "r"(a[0]), "r"(a[1]), "r"(a[2]), "r"(a[3]), "r"(b[0]), "r"(b[1]));
}

// MODE 0: grid (128,2,1): Ph = headH @ UTH^T   (writes fp16 vector layout)
// MODE 1: grid (16,16,8): out = Ph @ depH^T + hs + ds + bias
template <int MODE>
__global__ void __launch_bounds__(TH, 2)
gemm_kernel(float* __restrict__ out, const float* __restrict__ eb) {
    extern __shared__ float sm[];
    const uint32_t sb = smem_u32(sm);

    const int tid = threadIdx.x;
    const int w = tid >> 5, lane = tid & 31;
    const int wm = w >> 1;          // 0..1 (M warp: 64 rows)
    const int wn = w & 1;           // 0..1 (N warp: 64 cols)
    const int x = blockIdx.x, y = blockIdx.y, z = blockIdx.z;

    const __half *Atile, *Btile;
    if (MODE == 0) {
        Atile = g_headH + (size_t)x * 4 * TILE_H;
        Btile = g_UTH   + (size_t)y * 4 * TILE_H;
    } else {
        Atile = g_Ph   + (size_t)(z * 16 + x) * 4 * TILE_H;
        Btile = g_depH + (size_t)(z * 16 + y) * 4 * TILE_H;
    }

    if (MODE == 1) {
        float* sex = sm + EXTRA_OFF / 4;
        sex[tid]       = g_hs[(size_t)z * Sn + (size_t)x * BM + tid];
        sex[128 + tid] = g_ds[(size_t)z * Sn + (size_t)y * BN + tid];
    }

    auto load_chunk = [&](int kt) {
        int stg = kt % STAGES;
        uint32_t baseA = sb + (uint32_t)stg * STAGE_BYTES;
        uint32_t baseB = baseA + TILE_BYTES;
        const __half* gA = Atile + (size_t)kt * TILE_H;
        const __half* gB = Btile + (size_t)kt * TILE_H;
        #pragma unroll
        for (int i = 0; i < 8; i++) {
            int cid = i * 128 + tid;
            cpasync16(baseA + (uint32_t)cid * 16, gA + cid * 8);
        }
        #pragma unroll
        for (int i = 0; i < 8; i++) {
            int cid = i * 128 + tid;
            cpasync16(baseB + (uint32_t)cid * 16, gB + cid * 8);
        }
        asm volatile("cp.async.commit_group;" ::: "memory");
    };

    float acc[4][8][4];
    #pragma unroll
    for (int i = 0; i < 4; i++)
        #pragma unroll
        for (int j = 0; j < 8; j++)
            #pragma unroll
            for (int t = 0; t < 4; t++) acc[i][j][t] = 0.f;

    load_chunk(0);
    load_chunk(1);

    const int rq = lane >> 2;       // 0..7
    const int kq = lane & 3;        // 0..3
    const uint32_t qoff = (uint32_t)rq * 256;
    const uint32_t xr = ((uint32_t)rq & 1) << 2;

    #pragma unroll 1
    for (int kt = 0; kt < 4; kt++) {
        if (kt == 3) { asm volatile("cp.async.wait_group 0;" ::: "memory"); }
        else         { asm volatile("cp.async.wait_group 1;" ::: "memory"); }
        __syncthreads();
        if (kt + 2 < 4) load_chunk(kt + 2);

        int stg = kt % STAGES;
        uint32_t baseA = sb + (uint32_t)stg * STAGE_BYTES;
        uint32_t baseB = baseA + TILE_BYTES;

        #pragma unroll
        for (int ks = 0; ks < 4; ks++) {
            uint32_t slotOff = ((((uint32_t)(ks * 4 + kq)) ^ xr) << 4);

            uint32_t a[4][4];
            #pragma unroll
            for (int i = 0; i < 4; i++) {
                uint32_t m = (uint32_t)(wm * 4 + i);
                uint32_t ad = baseA + m * 2048 + qoff + slotOff;
                uint4 v;
                asm volatile("ld.shared.v4.b32 {%0,%1,%2,%3}, [%4];"
                             : "=r"(v.x), "=r"(v.y), "=r"(v.z), "=r"(v.w) : "r"(ad));
                a[i][0] = v.x; a[i][1] = v.y; a[i][2] = v.z; a[i][3] = v.w;
            }

            uint32_t b[8][2];
            #pragma unroll
            for (int jp = 0; jp < 4; jp++) {
                uint32_t m = (uint32_t)(wn * 4 + jp);
                uint32_t bd = baseB + m * 2048 + qoff + slotOff;
                uint4 v;
                asm volatile("ld.shared.v4.b32 {%0,%1,%2,%3}, [%4];"
                             : "=r"(v.x), "=r"(v.y), "=r"(v.z), "=r"(v.w) : "r"(bd));
                b[2 * jp][0]     = v.x;   // (n,   k01)
                b[2 * jp][1]     = v.z;   // (n,   k89)
                b[2 * jp + 1][0] = v.y;   // (n+8, k01)
                b[2 * jp + 1][1] = v.w;   // (n+8, k89)
            }

            #pragma unroll
            for (int i = 0; i < 4; i++)
                #pragma unroll
                for (int j = 0; j < 8; j++)
                    mma_f16(acc[i][j], a[i], b[j]);
        }
    }

    if (MODE == 0) {
        // write Ph in the same fp16 vector layout
        int kc = y * 2 + wn;
        #pragma unroll
        for (int i = 0; i < 4; i++) {
            int m = wm * 4 + i;
            #pragma unroll
            for (int jp = 0; jp < 4; jp++) {
                int slotpos = (jp * 4 + kq) ^ (int)xr;
                uint4 o;
                o.x = pack2(acc[i][2 * jp][0],     acc[i][2 * jp][1]);
                o.y = pack2(acc[i][2 * jp][2],     acc[i][2 * jp][3]);
                o.z = pack2(acc[i][2 * jp + 1][0], acc[i][2 * jp + 1][1]);
                o.w = pack2(acc[i][2 * jp + 1][2], acc[i][2 * jp + 1][3]);
                size_t off = ((size_t)(x * 4 + kc)) * TILE_H
                           + ((m * 8 + rq) * 16 + slotpos) * 8;
                *(uint4*)(g_Ph + off) = o;
            }
        }
    } else {
        float bias = __ldg(eb);
        const float* shs = sm + EXTRA_OFF / 4;
        const float* sds = shs + 128;
        size_t aRow0 = (size_t)z * Sn + (size_t)x * BM;
        #pragma unroll
        for (int i = 0; i < 4; i++) {
            int rl = wm * 64 + i * 16 + rq;
            float hs0 = shs[rl] + bias;
            float hs1 = shs[rl + 8] + bias;
            size_t gr0 = (aRow0 + rl) * (size_t)Sn + (size_t)y * BN;
            #pragma unroll
            for (int j = 0; j < 8; j++) {
                int c = wn * 64 + j * 8 + kq * 2;
                float d0 = sds[c], d1 = sds[c + 1];
                *(float2*)(out + gr0 + c) =
                    make_float2(acc[i][j][0] + hs0 + d0, acc[i][j][1] + hs0 + d1);
                *(float2*)(out + gr0 + 8 * (size_t)Sn + c) =
                    make_float2(acc[i][j][2] + hs1 + d0, acc[i][j][3] + hs1 + d1);
            }
        }
    }
}

// ---------------- kernel_launch ----------------
extern "C" void kernel_launch(void* const* d_in, const int* in_sizes, int n_in,
                              void* d_out, int out_size) {
    const float* head = (const float*)d_in[0];
    const float* dep  = (const float*)d_in[1];
    const float* U    = (const float*)d_in[2];
    const float* W    = (const float*)d_in[3];
    const float* eb   = (const float*)d_in[4];
    float* out = (float*)d_out;
    (void)in_sizes; (void)n_in; (void)out_size;

    cudaFuncSetAttribute(gemm_kernel<0>,
                         cudaFuncAttributeMaxDynamicSharedMemorySize, SMEM_BYTES);
    cudaFuncSetAttribute(gemm_kernel<1>,
                         cudaFuncAttributeMaxDynamicSharedMemorySize, SMEM_BYTES);

    // 1) prep: register-repack headH/depH + hs/ds dots; UTH transpose
    prep_all<<<HD_BLOCKS + UT_BLOCKS, 256>>>(head, dep, W, U);
    // 2) stage-1: Ph = headH @ UTH^T
    gemm_kernel<0><<<dim3(MROWS / BM, 2, 1), TH, SMEM_BYTES>>>(out, eb);
    // 3) stage-2: out[b] = Ph[b] @ depH[b]^T + hs + ds + bias
    gemm_kernel<1><<<dim3(Sn / BM, Sn / BN, Bn), TH, SMEM_BYTES>>>(out, eb);
}

// round 17
// speedup vs baseline: 1.0193x; 1.0193x over previous
#include <cuda_runtime.h>
#include <cuda_fp16.h>
#include <cstdint>

// Problem constants: B=8, S=2048, D=256
static constexpr int Bn = 8;
static constexpr int Sn = 2048;
static constexpr int Dn = 256;
static constexpr int MROWS = Bn * Sn;   // 16384

// ---------------- device scratch (no cudaMalloc allowed) ----------------
// Unified fp16 vector layout: tensors split into (128-row x 64-k) tiles of 16 KB.
// Vector (m,q,slotpos): slot = slotpos ^ ((q&1)<<2), k = (slot>>2)*16 + (slot&3)*2,
// r = 16m + q. Vector = {T[r][k],T[r][k+1], T[r+8][k],T[r+8][k+1],
//                        T[r][k+8],T[r][k+9], T[r+8][k+8],T[r+8][k+9]}.
__device__ __align__(16) __half g_headH[MROWS * Dn];
__device__ __align__(16) __half g_depH [MROWS * Dn];
__device__ __align__(16) __half g_Ph   [MROWS * Dn];
__device__ __align__(16) __half g_UTH  [Dn * Dn];
__device__ float g_hs[MROWS];
__device__ float g_ds[MROWS];

static constexpr int TILE_H = 8192;     // halves per (128x64) tile

__device__ __forceinline__ uint32_t pack2(float lo, float hi) {
    __half2 h = __floats2half2_rn(lo, hi);
    return *(uint32_t*)&h;
}
__device__ __forceinline__ uint32_t smem_u32(const void* p) {
    uint32_t a;
    asm("{ .reg .u64 t; cvta.to.shared.u64 t, %1; cvt.u32.u64 %0, t; }"
        : "=r"(a) : "l"(p));
    return a;
}
__device__ __forceinline__ void cpasync16(uint32_t dst, const void* src) {
    size_t g = __cvta_generic_to_global(src);
    asm volatile("cp.async.cg.shared.global [%0], [%1], 16;" :: "r"(dst), "l"(g));
}

// ---------------- prep: head->hs+headH | dep->ds+depH | U->UTH ----------------
static constexpr int HEAD_BLOCKS = MROWS / 16;   // 1024
static constexpr int DEP_BLOCKS = MROWS / 16;    // 1024
static constexpr int UT_BLOCKS = 16;

__global__ void __launch_bounds__(256) prep_all(const float* __restrict__ head,
                                                const float* __restrict__ dep,
                                                const float* __restrict__ W,
                                                const float* __restrict__ U) {
    __shared__ float s[16][264];
    int bid = blockIdx.x;
    int tid = threadIdx.x, w = tid >> 5, lane = tid & 31;

    __half* dstH;
    float* dotDst = nullptr;
    const float* wvp = nullptr;
    int r0;            // 16-row base within the tensor's row space

    if (bid < HEAD_BLOCKS + DEP_BLOCKS) {
        bool isHead = bid < HEAD_BLOCKS;
        const float* src = isHead ? head : dep;
        dstH   = isHead ? g_headH : g_depH;
        dotDst = isHead ? g_hs : g_ds;
        wvp    = isHead ? W : (W + Dn);
        r0 = (isHead ? bid : bid - HEAD_BLOCKS) * 16;
        // cp.async staging: 16 rows x 256 floats = one contiguous 16 KB span
        const float* srcb = src + (size_t)r0 * Dn;
        uint32_t sbase = smem_u32(&s[0][0]);
        #pragma unroll
        for (int it = 0; it < 4; it++) {
            int v = it * 256 + tid;             // 0..1023 (16B units)
            int row = v >> 6, c = v & 63;
            cpasync16(sbase + (uint32_t)(row * 1056 + c * 16), srcb + v * 4);
        }
        asm volatile("cp.async.commit_group;" ::: "memory");
        asm volatile("cp.async.wait_group 0;" ::: "memory");
        __syncthreads();
    } else {
        // UT rows e, cols d: s[e'][d] = U[d][r0+e']
        int tb = bid - HEAD_BLOCKS - DEP_BLOCKS;
        r0 = tb * 16;
        dstH = g_UTH;
        #pragma unroll
        for (int i = 0; i < 16; i++) {
            int d = i * 16 + (tid >> 4);
            int e = tid & 15;
            s[e][d] = U[(size_t)d * Dn + r0 + e];
        }
        __syncthreads();
    }

    // row dots (head/dep only): warp w handles rows 2w, 2w+1 (float4 smem reads)
    if (dotDst) {
        float4 w0 = *(const float4*)(wvp + lane * 8);
        float4 w1 = *(const float4*)(wvp + lane * 8 + 4);
        #pragma unroll
        for (int rw = 0; rw < 2; rw++) {
            int row = w * 2 + rw;
            float4 a0 = *(const float4*)&s[row][lane * 8];
            float4 a1 = *(const float4*)&s[row][lane * 8 + 4];
            float p = a0.x * w0.x + a0.y * w0.y + a0.z * w0.z + a0.w * w0.w
                    + a1.x * w1.x + a1.y * w1.y + a1.z * w1.z + a1.w * w1.w;
            #pragma unroll
            for (int o = 16; o; o >>= 1) p += __shfl_down_sync(0xFFFFFFFFu, p, o);
            if (lane == 0) dotDst[r0 + row] = p;
        }
    }

    // emit 512 vectors (4 kc x 8 q x 16 slotpos), 2 per thread; float2 smem reads
    int rowtile = r0 >> 7;
    int m = (r0 & 127) >> 4;
    #pragma unroll
    for (int it = 0; it < 2; it++) {
        int v = it * 256 + tid;                 // 0..511
        int kc = v >> 7;
        int u = v & 127;
        int q = u >> 4;                         // 0..7
        int slotpos = u & 15;
        int slot = slotpos ^ ((q & 1) << 2);
        int k = kc * 64 + (slot >> 2) * 16 + (slot & 3) * 2;
        float2 f0 = *(const float2*)&s[q][k];
        float2 f1 = *(const float2*)&s[q + 8][k];
        float2 f2 = *(const float2*)&s[q][k + 8];
        float2 f3 = *(const float2*)&s[q + 8][k + 8];
        uint4 o;
        o.x = pack2(f0.x, f0.y);
        o.y = pack2(f1.x, f1.y);
        o.z = pack2(f2.x, f2.y);
        o.w = pack2(f3.x, f3.y);
        size_t off = ((size_t)(rowtile * 4 + kc)) * TILE_H
                   + ((m * 8 + q) * 16 + slotpos) * 8;
        *(uint4*)(dstH + off) = o;
    }
}

// ---------------- fp16 MMA GEMM: CTA 128x128, 4 warps, warp tile 64x64, BK=64 ----------------
static constexpr int BM = 128, BN = 128, TH = 128;
static constexpr int STAGES = 3;
static constexpr uint32_t TILE_BYTES = 16384;                 // 128x64 fp16
static constexpr uint32_t STAGE_BYTES = 2 * TILE_BYTES;       // A + B
static constexpr uint32_t EXTRA_OFF = STAGES * STAGE_BYTES;   // 98304
static constexpr uint32_t SMEM_BYTES = EXTRA_OFF + 1024;

__device__ __forceinline__ void mma_f16(float* c, const uint32_t* a, const uint32_t* b) {
    asm volatile(
        "mma.sync.aligned.m16n8k16.row.col.f32.f16.f16.f32 "
        "{%0,%1,%2,%3}, {%4,%5,%6,%7}, {%8,%9}, {%0,%1,%2,%3};"
        : "+f"(c[0]), "+f"(c[1]), "+f"(c[2]), "+f"(c[3])
        : "r"(a[0]), "r"(a[1]), "r"(a[2]), "r"(a[3]), "r"(b[0]), "r"(b[1]));
}

// MODE 0: grid (128,2,1): Ph = headH @ UTH^T   (writes fp16 vector layout)
// MODE 1: grid (16,16,8): out = Ph @ depH^T + hs + ds + bias
template <int MODE>
__global__ void __launch_bounds__(TH, 2)
gemm_kernel(float* __restrict__ out, const float* __restrict__ eb) {
    extern __shared__ float sm[];
    const uint32_t sb = smem_u32(sm);

    const int tid = threadIdx.x;
    const int w = tid >> 5, lane = tid & 31;
    const int wm = w >> 1;          // 0..1 (M warp: 64 rows)
    const int wn = w & 1;           // 0..1 (N warp: 64 cols)
    const int x = blockIdx.x, y = blockIdx.y, z = blockIdx.z;

    const __half *Atile, *Btile;
    if (MODE == 0) {
        Atile = g_headH + (size_t)x * 4 * TILE_H;
        Btile = g_UTH   + (size_t)y * 4 * TILE_H;
    } else {
        Atile = g_Ph   + (size_t)(z * 16 + x) * 4 * TILE_H;
        Btile = g_depH + (size_t)(z * 16 + y) * 4 * TILE_H;
    }

    if (MODE == 1) {
        float* sex = sm + EXTRA_OFF / 4;
        sex[tid]       = g_hs[(size_t)z * Sn + (size_t)x * BM + tid];
        sex[128 + tid] = g_ds[(size_t)z * Sn + (size_t)y * BN + tid];
    }

    auto load_chunk = [&](int kt) {
        int stg = kt % STAGES;
        uint32_t baseA = sb + (uint32_t)stg * STAGE_BYTES;
        uint32_t baseB = baseA + TILE_BYTES;
        const __half* gA = Atile + (size_t)kt * TILE_H;
        const __half* gB = Btile + (size_t)kt * TILE_H;
        #pragma unroll
        for (int i = 0; i < 8; i++) {
            int cid = i * 128 + tid;
            cpasync16(baseA + (uint32_t)cid * 16, gA + cid * 8);
        }
        #pragma unroll
        for (int i = 0; i < 8; i++) {
            int cid = i * 128 + tid;
            cpasync16(baseB + (uint32_t)cid * 16, gB + cid * 8);
        }
        asm volatile("cp.async.commit_group;" ::: "memory");
    };

    float acc[4][8][4];
    #pragma unroll
    for (int i = 0; i < 4; i++)
        #pragma unroll
        for (int j = 0; j < 8; j++)
            #pragma unroll
            for (int t = 0; t < 4; t++) acc[i][j][t] = 0.f;

    load_chunk(0);
    load_chunk(1);

    const int rq = lane >> 2;       // 0..7
    const int kq = lane & 3;        // 0..3
    const uint32_t qoff = (uint32_t)rq * 256;
    const uint32_t xr = ((uint32_t)rq & 1) << 2;

    #pragma unroll 1
    for (int kt = 0; kt < 4; kt++) {
        if (kt == 3) { asm volatile("cp.async.wait_group 0;" ::: "memory"); }
        else         { asm volatile("cp.async.wait_group 1;" ::: "memory"); }
        __syncthreads();
        if (kt + 2 < 4) load_chunk(kt + 2);

        int stg = kt % STAGES;
        uint32_t baseA = sb + (uint32_t)stg * STAGE_BYTES;
        uint32_t baseB = baseA + TILE_BYTES;

        #pragma unroll
        for (int ks = 0; ks < 4; ks++) {
            uint32_t slotOff = ((((uint32_t)(ks * 4 + kq)) ^ xr) << 4);

            uint32_t a[4][4];
            #pragma unroll
            for (int i = 0; i < 4; i++) {
                uint32_t m = (uint32_t)(wm * 4 + i);
                uint32_t ad = baseA + m * 2048 + qoff + slotOff;
                uint4 v;
                asm volatile("ld.shared.v4.b32 {%0,%1,%2,%3}, [%4];"
                             : "=r"(v.x), "=r"(v.y), "=r"(v.z), "=r"(v.w) : "r"(ad));
                a[i][0] = v.x; a[i][1] = v.y; a[i][2] = v.z; a[i][3] = v.w;
            }

            uint32_t b[8][2];
            #pragma unroll
            for (int jp = 0; jp < 4; jp++) {
                uint32_t m = (uint32_t)(wn * 4 + jp);
                uint32_t bd = baseB + m * 2048 + qoff + slotOff;
                uint4 v;
                asm volatile("ld.shared.v4.b32 {%0,%1,%2,%3}, [%4];"
                             : "=r"(v.x), "=r"(v.y), "=r"(v.z), "=r"(v.w) : "r"(bd));
                b[2 * jp][0]     = v.x;   // (n,   k01)
                b[2 * jp][1]     = v.z;   // (n,   k89)
                b[2 * jp + 1][0] = v.y;   // (n+8, k01)
                b[2 * jp + 1][1] = v.w;   // (n+8, k89)
            }

            #pragma unroll
            for (int i = 0; i < 4; i++)
                #pragma unroll
                for (int j = 0; j < 8; j++)
                    mma_f16(acc[i][j], a[i], b[j]);
        }
    }

    if (MODE == 0) {
        // write Ph in the same fp16 vector layout
        int kc = y * 2 + wn;
        #pragma unroll
        for (int i = 0; i < 4; i++) {
            int m = wm * 4 + i;
            #pragma unroll
            for (int jp = 0; jp < 4; jp++) {
                int slotpos = (jp * 4 + kq) ^ (int)xr;
                uint4 o;
                o.x = pack2(acc[i][2 * jp][0],     acc[i][2 * jp][1]);
                o.y = pack2(acc[i][2 * jp][2],     acc[i][2 * jp][3]);
                o.z = pack2(acc[i][2 * jp + 1][0], acc[i][2 * jp + 1][1]);
                o.w = pack2(acc[i][2 * jp + 1][2], acc[i][2 * jp + 1][3]);
                size_t off = ((size_t)(x * 4 + kc)) * TILE_H
                           + ((m * 8 + rq) * 16 + slotpos) * 8;
                *(uint4*)(g_Ph + off) = o;
            }
        }
    } else {
        float bias = __ldg(eb);
        const float* shs = sm + EXTRA_OFF / 4;
        const float* sds = shs + 128;
        size_t aRow0 = (size_t)z * Sn + (size_t)x * BM;
        #pragma unroll
        for (int i = 0; i < 4; i++) {
            int rl = wm * 64 + i * 16 + rq;
            float hs0 = shs[rl] + bias;
            float hs1 = shs[rl + 8] + bias;
            size_t gr0 = (aRow0 + rl) * (size_t)Sn + (size_t)y * BN;
            #pragma unroll
            for (int j = 0; j < 8; j++) {
                int c = wn * 64 + j * 8 + kq * 2;
                float d0 = sds[c], d1 = sds[c + 1];
                *(float2*)(out + gr0 + c) =
                    make_float2(acc[i][j][0] + hs0 + d0, acc[i][j][1] + hs0 + d1);
                *(float2*)(out + gr0 + 8 * (size_t)Sn + c) =
                    make_float2(acc[i][j][2] + hs1 + d0, acc[i][j][3] + hs1 + d1);
            }
        }
    }
}

// ---------------- kernel_launch ----------------
extern "C" void kernel_launch(void* const* d_in, const int* in_sizes, int n_in,
                              void* d_out, int out_size) {
    const float* head = (const float*)d_in[0];
    const float* dep  = (const float*)d_in[1];
    const float* U    = (const float*)d_in[2];
    const float* W    = (const float*)d_in[3];
    const float* eb   = (const float*)d_in[4];
    float* out = (float*)d_out;
    (void)in_sizes; (void)n_in; (void)out_size;

    cudaFuncSetAttribute(gemm_kernel<0>,
                         cudaFuncAttributeMaxDynamicSharedMemorySize, SMEM_BYTES);
    cudaFuncSetAttribute(gemm_kernel<1>,
                         cudaFuncAttributeMaxDynamicSharedMemorySize, SMEM_BYTES);

    // 1) prep: cp.async-staged hs/ds dots + fp16 vector-layout headH/depH/UTH
    prep_all<<<HEAD_BLOCKS + DEP_BLOCKS + UT_BLOCKS, 256>>>(head, dep, W, U);
    // 2) stage-1: Ph = headH @ UTH^T
    gemm_kernel<0><<<dim3(MROWS / BM, 2, 1), TH, SMEM_BYTES>>>(out, eb);
    // 3) stage-2: out[b] = Ph[b] @ depH[b]^T + hs + ds + bias
    gemm_kernel<1><<<dim3(Sn / BM, Sn / BN, Bn), TH, SMEM_BYTES>>>(out, eb);
}